// round 3
// baseline (speedup 1.0000x reference)
#include <cuda_runtime.h>
#include <cstdio>

#define NND 20
#define CHN 512
#define HH  64
#define WW  64
#define HW  4096
#define CHW 2097152   // 512*64*64

// Big scratch: [V:1][Gr,Gu,Go:3][cs:1][rh:1][U:1][O:1][h:20][R:20] = 48 planes
__device__ float g_buf[48ll * CHW];
__device__ float g_b[NND * CHN];            // per-node channel bias (lang part + mconv_b)
__device__ float g_t[3 * NND * 9 * CHN];    // per-gate per-node per-tap constant vectors
__device__ int   g_childcount[NND];
__device__ int   g_child[NND * NND];

__device__ __forceinline__ float sigm(float v) { return 1.f / (1.f + expf(-v)); }

// ---------------------------------------------------------------------------
// Tree prep: child lists + counts from adjacency (adj[p*20+c] != 0 => c child of p)
// ---------------------------------------------------------------------------
__global__ void prep_kernel(const int* __restrict__ adj) {
    int n = threadIdx.x;
    if (n < NND) {
        int cnt = 0;
        for (int k = 0; k < NND; k++)
            if (adj[n * NND + k] != 0) g_child[n * NND + cnt++] = k;
        g_childcount[n] = cnt;
    }
}

// ---------------------------------------------------------------------------
// b[n][o] = mconv_b[o] + sum_i mconv_w[o, 512+i] * lang[n, i]
// ---------------------------------------------------------------------------
__global__ void langbias_kernel(const float* __restrict__ lang,
                                const float* __restrict__ mw,
                                const float* __restrict__ mb) {
    int idx = blockIdx.x * 256 + threadIdx.x;
    if (idx >= NND * CHN) return;
    int n = idx / CHN, o = idx - n * CHN;
    const float* wp = mw + o * 812 + 512;
    const float* lp = lang + n * 300;
    float acc = mb[o];
    for (int i = 0; i < 300; i++) acc += wp[i] * lp[i];
    g_b[idx] = acc;
}

// ---------------------------------------------------------------------------
// t[g][n][tap][o] = sum_{i<512} Wg_x[o,i,tap] * b[n][i]
// one thread per (g,tap,o), computes all 20 n. 54 blocks x 256.
// ---------------------------------------------------------------------------
__global__ void tapconst_kernel(const float* __restrict__ rw,
                                const float* __restrict__ uw,
                                const float* __restrict__ ow) {
    __shared__ float bs[NND * CHN];  // 40KB
    int tid = threadIdx.x;
    for (int idx = tid; idx < NND * CHN; idx += 256) bs[idx] = g_b[idx];
    __syncthreads();
    int gidx = blockIdx.x * 256 + tid;       // 3*9*512 = 13824
    int o   = gidx & (CHN - 1);
    int tap = (gidx >> 9) % 9;
    int g   = gidx / (CHN * 9);
    const float* w = (g == 0) ? rw : (g == 1) ? uw : ow;
    const float* wp = w + o * 9216 + tap;    // i-stride 9, i in [0,512) = x-part
    float acc[NND];
#pragma unroll
    for (int n = 0; n < NND; n++) acc[n] = 0.f;
    for (int i = 0; i < CHN; i++) {
        float wv = wp[i * 9];
#pragma unroll
        for (int n = 0; n < NND; n++) acc[n] += wv * bs[n * CHN + i];
    }
#pragma unroll
    for (int n = 0; n < NND; n++)
        g_t[((g * NND + n) * 9 + tap) * CHN + o] = acc[n];
}

// ---------------------------------------------------------------------------
// GEMM: out[o][p] = sum_{i<K} w[o*ldw + i] * in[i*4096 + p]   (V = vis @ W_vis)
// block: 64 o x 128 p, 128 threads, thread: 8o x 8p (p strided by 16)
// ---------------------------------------------------------------------------
__global__ __launch_bounds__(128) void gemm_kernel(
    const float* __restrict__ in, const float* __restrict__ w,
    int ldw, int K, float* __restrict__ out) {
    __shared__ float xs[8 * 128];
    __shared__ float wsm[8 * 65];
    int pB  = blockIdx.x * 128;
    int coB = blockIdx.y * 64;
    int tid = threadIdx.x;
    int pxg = tid & 15, cog = tid >> 4;
    float acc[8][8];
#pragma unroll
    for (int a = 0; a < 8; a++)
#pragma unroll
        for (int b = 0; b < 8; b++) acc[a][b] = 0.f;

    for (int kb = 0; kb < K; kb += 8) {
        __syncthreads();
        for (int idx = tid; idx < 1024; idx += 128) {
            int i = idx >> 7, p = idx & 127;
            xs[idx] = in[(kb + i) * HW + pB + p];
        }
        for (int idx = tid; idx < 512; idx += 128) {
            int co = idx >> 3, i = idx & 7;
            wsm[i * 65 + co] = w[(coB + co) * ldw + kb + i];
        }
        __syncthreads();
#pragma unroll
        for (int i = 0; i < 8; i++) {
            float xv[8], wv[8];
#pragma unroll
            for (int v = 0; v < 8; v++) xv[v] = xs[i * 128 + pxg + 16 * v];
#pragma unroll
            for (int u = 0; u < 8; u++) wv[u] = wsm[i * 65 + u * 8 + cog];
#pragma unroll
            for (int u = 0; u < 8; u++)
#pragma unroll
                for (int v = 0; v < 8; v++)
                    acc[u][v] = fmaf(wv[u], xv[v], acc[u][v]);
        }
    }
#pragma unroll
    for (int u = 0; u < 8; u++) {
        float* op = out + (coB + u * 8 + cog) * HW + pB + pxg;
#pragma unroll
        for (int v = 0; v < 8; v++) op[16 * v] = acc[u][v];
    }
}

// ---------------------------------------------------------------------------
// Direct 3x3 conv, pad=1, 512ch -> 512ch over 64x64, fp32.
// weights: wbase[(o)*9216 + (w_coff + i)*9 + ky*3 + kx], i in [0,512)
// block: 64 cout x (8 rows x 16 cols), 128 threads, thread: 8co x 8px.
// flag_n >= 0 : skip entirely if g_childcount[flag_n] == 0  (leaf skip)
// ---------------------------------------------------------------------------
__global__ __launch_bounds__(128) void conv3x3_kernel(
    const float* __restrict__ in, const float* __restrict__ wbase,
    int w_coff, float* __restrict__ out, int flag_n) {
    if (flag_n >= 0 && g_childcount[flag_n] == 0) return;

    __shared__ float xs[8 * 10 * 21];   // 8 ci x 10 rows x (18 cols, pitch 21)
    __shared__ float wsm[8 * 9 * 65];   // [ci][tap][co], co pitch 65

    int sp  = blockIdx.x;               // 32 spatial tiles
    int coB = blockIdx.y * 64;
    int ty = sp >> 2, tx = sp & 3;
    int y0 = ty * 8, x0 = tx * 16;

    int tid = threadIdx.x;
    int pxg = tid & 15;
    int cog = tid >> 4;                 // 0..7
    int r   = pxg >> 1;                 // 0..7 row within tile
    int chf = (pxg & 1) * 8;            // col half: 0 or 8

    float acc[8][8];
#pragma unroll
    for (int a = 0; a < 8; a++)
#pragma unroll
        for (int b = 0; b < 8; b++) acc[a][b] = 0.f;

    for (int cb = 0; cb < CHN; cb += 8) {
        __syncthreads();
        // input tile: 8 ci x 10 x 18 with zero halo
        for (int idx = tid; idx < 8 * 10 * 18; idx += 128) {
            int ci  = idx / 180;
            int rem = idx - ci * 180;
            int ry  = rem / 18;
            int rx  = rem - ry * 18;
            int gy = y0 + ry - 1, gx = x0 + rx - 1;
            float v = 0.f;
            if (gy >= 0 && gy < HH && gx >= 0 && gx < WW)
                v = in[(cb + ci) * HW + gy * WW + gx];
            xs[(ci * 10 + ry) * 21 + rx] = v;
        }
        // weights: 64 co x (8 ci x 9 taps), coalesced 72-float runs per co
        for (int idx = tid; idx < 64 * 72; idx += 128) {
            int co  = idx / 72;
            int t72 = idx - co * 72;    // = ci*9 + tap
            wsm[t72 * 65 + co] =
                wbase[(coB + co) * 9216 + (w_coff + cb) * 9 + t72];
        }
        __syncthreads();
#pragma unroll 1
        for (int ci = 0; ci < 8; ci++) {
#pragma unroll
            for (int ky = 0; ky < 3; ky++) {
                float xr[10];
#pragma unroll
                for (int j = 0; j < 10; j++)
                    xr[j] = xs[(ci * 10 + r + ky) * 21 + chf + j];
#pragma unroll
                for (int kx = 0; kx < 3; kx++) {
                    float wv[8];
#pragma unroll
                    for (int u = 0; u < 8; u++)
                        wv[u] = wsm[(ci * 9 + ky * 3 + kx) * 65 + u * 8 + cog];
#pragma unroll
                    for (int u = 0; u < 8; u++)
#pragma unroll
                        for (int v = 0; v < 8; v++)
                            acc[u][v] = fmaf(wv[u], xr[v + kx], acc[u][v]);
                }
            }
        }
    }
    int py = y0 + r, pxc = x0 + chf;
#pragma unroll
    for (int u = 0; u < 8; u++) {
        float4* op = reinterpret_cast<float4*>(
            out + (coB + u * 8 + cog) * HW + py * WW + pxc);
        op[0] = make_float4(acc[u][0], acc[u][1], acc[u][2], acc[u][3]);
        op[1] = make_float4(acc[u][4], acc[u][5], acc[u][6], acc[u][7]);
    }
}

// ---------------------------------------------------------------------------
// gather: for node n with children:
//   cs = sum_k h[k];  rh = sum_k sigmoid(Gr + cr_n(pix) + reset_b + R[k]) * h[k]
// ---------------------------------------------------------------------------
__global__ void gather_kernel(int n, const float* __restrict__ reset_b) {
    int cnt = g_childcount[n];
    if (cnt == 0) return;
    int e = blockIdx.x * 256 + threadIdx.x;
    int c = e >> 12;
    int p = e & (HW - 1);
    int y = p >> 6, x = p & 63;
    const float* t = g_t + (0 * NND + n) * 9 * CHN;
    int ky0 = (y == 0), ky1 = 2 - (y == HH - 1);
    int kx0 = (x == 0), kx1 = 2 - (x == WW - 1);
    float cr = 0.f;
    for (int ky = ky0; ky <= ky1; ky++)
        for (int kx = kx0; kx <= kx1; kx++)
            cr += t[(ky * 3 + kx) * CHN + c];
    float base = g_buf[1 * CHW + e] + reset_b[c] + cr;  // Gr
    float cs = 0.f, rh = 0.f;
    for (int j = 0; j < cnt; j++) {
        int k = g_child[n * NND + j];
        float hv = g_buf[(8 + k) * CHW + e];
        float rr = sigm(base + g_buf[(28 + k) * CHW + e]);
        cs += hv;
        rh += rr * hv;
    }
    g_buf[4 * CHW + e] = cs;   // cs
    g_buf[5 * CHW + e] = rh;   // rh
}

// ---------------------------------------------------------------------------
// combine: h[n] = (1-z)*tanh(Go + co_n + output_b + O) + z*cs
//          z    = sigmoid(Gu + cu_n + update_b + U)
// leaves: U = O = cs = 0
// ---------------------------------------------------------------------------
__global__ void combine_kernel(int n, const float* __restrict__ update_b,
                               const float* __restrict__ output_b,
                               float* __restrict__ dst) {
    int e = blockIdx.x * 256 + threadIdx.x;
    int c = e >> 12;
    int p = e & (HW - 1);
    int y = p >> 6, x = p & 63;
    bool haskids = g_childcount[n] > 0;
    const float* tu = g_t + (1 * NND + n) * 9 * CHN;
    const float* to = g_t + (2 * NND + n) * 9 * CHN;
    int ky0 = (y == 0), ky1 = 2 - (y == HH - 1);
    int kx0 = (x == 0), kx1 = 2 - (x == WW - 1);
    float cu = 0.f, co = 0.f;
    for (int ky = ky0; ky <= ky1; ky++)
        for (int kx = kx0; kx <= kx1; kx++) {
            int oidx = (ky * 3 + kx) * CHN + c;
            cu += tu[oidx];
            co += to[oidx];
        }
    float uacc = haskids ? g_buf[6 * CHW + e] : 0.f;
    float oacc = haskids ? g_buf[7 * CHW + e] : 0.f;
    float cs   = haskids ? g_buf[4 * CHW + e] : 0.f;
    float z  = sigm(g_buf[2 * CHW + e] + update_b[c] + cu + uacc);
    float ri = tanhf(g_buf[3 * CHW + e] + output_b[c] + co + oacc);
    dst[e] = (1.f - z) * ri + z * cs;
}

// ---------------------------------------------------------------------------
extern "C" void kernel_launch(void* const* d_in, const int* in_sizes, int n_in,
                              void* d_out, int out_size) {
    const float* vis  = (const float*)d_in[0];
    const float* lang = (const float*)d_in[1];
    const int*   adj  = (const int*)d_in[2];
    const float* mw   = (const float*)d_in[3];
    const float* mb   = (const float*)d_in[4];
    const float* rw   = (const float*)d_in[5];
    const float* rb   = (const float*)d_in[6];
    const float* uw   = (const float*)d_in[7];
    const float* ub   = (const float*)d_in[8];
    const float* ow   = (const float*)d_in[9];
    const float* ob   = (const float*)d_in[10];
    float* out = (float*)d_out;

    float* buf = nullptr;
    cudaGetSymbolAddress((void**)&buf, g_buf);

    dim3 cgrid(32, 8);

    prep_kernel<<<1, 32>>>(adj);
    langbias_kernel<<<40, 256>>>(lang, mw, mb);
    tapconst_kernel<<<54, 256>>>(rw, uw, ow);

    // V = conv1x1(vis, mconv_w[:, :512])   (bias folded into b_n)
    gemm_kernel<<<cgrid, 128>>>(vis, mw, 812, 512, buf);

    // shared convs of V with each gate's x-part weights
    conv3x3_kernel<<<cgrid, 128>>>(buf, rw, 0, buf + 1 * CHW, -1);  // Gr
    conv3x3_kernel<<<cgrid, 128>>>(buf, uw, 0, buf + 2 * CHW, -1);  // Gu
    conv3x3_kernel<<<cgrid, 128>>>(buf, ow, 0, buf + 3 * CHW, -1);  // Go

    // nodes in decreasing index = valid topological order (parent(i) < i)
    for (int n = NND - 1; n >= 0; n--) {
        gather_kernel<<<8192, 256>>>(n, rb);
        // U = conv3x3(cs, Wu_h), O = conv3x3(rh, Wo_h)  (skipped for leaves)
        conv3x3_kernel<<<cgrid, 128>>>(buf + 4 * CHW, uw, 512, buf + 6 * CHW, n);
        conv3x3_kernel<<<cgrid, 128>>>(buf + 5 * CHW, ow, 512, buf + 7 * CHW, n);
        combine_kernel<<<8192, 256>>>(n, ub, ob,
                                      (n == 0) ? out : buf + (8 + n) * CHW);
        if (n > 0)  // R[n] = conv3x3(h[n], Wr_h) for the parent's reset gates
            conv3x3_kernel<<<cgrid, 128>>>(buf + (8 + n) * CHW, rw, 512,
                                           buf + (28 + n) * CHW, -1);
    }
}

// round 4
// speedup vs baseline: 1.0007x; 1.0007x over previous
#include <cuda_runtime.h>
#include <cstdio>

#define NND 20
#define CHN 512
#define HH  64
#define WW  64
#define HW  4096
#define CHW 2097152   // 512*64*64

// Big scratch: [V:1][Gr,Gu,Go:3][cs:1][rh:1][U:1][O:1][h:20][R:20] = 48 planes
__device__ float g_buf[48ll * CHW];
__device__ float g_b[NND * CHN];            // per-node channel bias (lang part + mconv_b)
__device__ float g_t[3 * NND * 9 * CHN];    // per-gate per-node per-tap constant vectors
__device__ int   g_childcount[NND];
__device__ int   g_child[NND * NND];

__device__ __forceinline__ float sigm(float v) { return 1.f / (1.f + expf(-v)); }

// ---------------------------------------------------------------------------
// Tree prep: child lists + counts from adjacency (adj[p*20+c] != 0 => c child of p)
// ---------------------------------------------------------------------------
__global__ void prep_kernel(const int* __restrict__ adj) {
    int n = threadIdx.x;
    if (n < NND) {
        int cnt = 0;
        for (int k = 0; k < NND; k++)
            if (adj[n * NND + k] != 0) g_child[n * NND + cnt++] = k;
        g_childcount[n] = cnt;
    }
}

// ---------------------------------------------------------------------------
// b[n][o] = mconv_b[o] + sum_i mconv_w[o, 512+i] * lang[n, i]
// ---------------------------------------------------------------------------
__global__ void langbias_kernel(const float* __restrict__ lang,
                                const float* __restrict__ mw,
                                const float* __restrict__ mb) {
    int idx = blockIdx.x * 256 + threadIdx.x;
    if (idx >= NND * CHN) return;
    int n = idx / CHN, o = idx - n * CHN;
    const float* wp = mw + o * 812 + 512;
    const float* lp = lang + n * 300;
    float acc = mb[o];
    for (int i = 0; i < 300; i++) acc += wp[i] * lp[i];
    g_b[idx] = acc;
}

// ---------------------------------------------------------------------------
// t[g][n][tap][o] = sum_{i<512} Wg_x[o,i,tap] * b[n][i]
// one thread per (g,tap,o), computes all 20 n. 54 blocks x 256.
// ---------------------------------------------------------------------------
__global__ void tapconst_kernel(const float* __restrict__ rw,
                                const float* __restrict__ uw,
                                const float* __restrict__ ow) {
    __shared__ float bs[NND * CHN];  // 40KB
    int tid = threadIdx.x;
    for (int idx = tid; idx < NND * CHN; idx += 256) bs[idx] = g_b[idx];
    __syncthreads();
    int gidx = blockIdx.x * 256 + tid;       // 3*9*512 = 13824
    int o   = gidx & (CHN - 1);
    int tap = (gidx >> 9) % 9;
    int g   = gidx / (CHN * 9);
    const float* w = (g == 0) ? rw : (g == 1) ? uw : ow;
    const float* wp = w + o * 9216 + tap;    // i-stride 9, i in [0,512) = x-part
    float acc[NND];
#pragma unroll
    for (int n = 0; n < NND; n++) acc[n] = 0.f;
    for (int i = 0; i < CHN; i++) {
        float wv = wp[i * 9];
#pragma unroll
        for (int n = 0; n < NND; n++) acc[n] += wv * bs[n * CHN + i];
    }
#pragma unroll
    for (int n = 0; n < NND; n++)
        g_t[((g * NND + n) * 9 + tap) * CHN + o] = acc[n];
}

// ---------------------------------------------------------------------------
// GEMM: out[o][p] = sum_{i<K} w[o*ldw + i] * in[i*4096 + p]   (V = vis @ W_vis)
// block: 64 o x 128 p, 128 threads, thread: 8o x 8p (p strided by 16)
// ---------------------------------------------------------------------------
__global__ __launch_bounds__(128) void gemm_kernel(
    const float* __restrict__ in, const float* __restrict__ w,
    int ldw, int K, float* __restrict__ out) {
    __shared__ float xs[8 * 128];
    __shared__ float wsm[8 * 65];
    int pB  = blockIdx.x * 128;
    int coB = blockIdx.y * 64;
    int tid = threadIdx.x;
    int pxg = tid & 15, cog = tid >> 4;
    float acc[8][8];
#pragma unroll
    for (int a = 0; a < 8; a++)
#pragma unroll
        for (int b = 0; b < 8; b++) acc[a][b] = 0.f;

    for (int kb = 0; kb < K; kb += 8) {
        __syncthreads();
        for (int idx = tid; idx < 1024; idx += 128) {
            int i = idx >> 7, p = idx & 127;
            xs[idx] = in[(kb + i) * HW + pB + p];
        }
        for (int idx = tid; idx < 512; idx += 128) {
            int co = idx >> 3, i = idx & 7;
            wsm[i * 65 + co] = w[(coB + co) * ldw + kb + i];
        }
        __syncthreads();
#pragma unroll
        for (int i = 0; i < 8; i++) {
            float xv[8], wv[8];
#pragma unroll
            for (int v = 0; v < 8; v++) xv[v] = xs[i * 128 + pxg + 16 * v];
#pragma unroll
            for (int u = 0; u < 8; u++) wv[u] = wsm[i * 65 + u * 8 + cog];
#pragma unroll
            for (int u = 0; u < 8; u++)
#pragma unroll
                for (int v = 0; v < 8; v++)
                    acc[u][v] = fmaf(wv[u], xv[v], acc[u][v]);
        }
    }
#pragma unroll
    for (int u = 0; u < 8; u++) {
        float* op = out + (coB + u * 8 + cog) * HW + pB + pxg;
#pragma unroll
        for (int v = 0; v < 8; v++) op[16 * v] = acc[u][v];
    }
}

// ---------------------------------------------------------------------------
// Direct 3x3 conv, pad=1, 512ch -> 512ch over 64x64, fp32.
// weights: wbase[(o)*9216 + (w_coff + i)*9 + ky*3 + kx], i in [0,512)
// block: 64 cout x (8 rows x 16 cols), 128 threads, thread: 8co x 8px.
// flag_n >= 0 : skip entirely if g_childcount[flag_n] == 0  (leaf skip)
// ---------------------------------------------------------------------------
__global__ __launch_bounds__(128) void conv3x3_kernel(
    const float* __restrict__ in, const float* __restrict__ wbase,
    int w_coff, float* __restrict__ out, int flag_n) {
    if (flag_n >= 0 && g_childcount[flag_n] == 0) return;

    __shared__ float xs[8 * 10 * 21];   // 8 ci x 10 rows x (18 cols, pitch 21)
    __shared__ float wsm[8 * 9 * 65];   // [ci][tap][co], co pitch 65

    int sp  = blockIdx.x;               // 32 spatial tiles
    int coB = blockIdx.y * 64;
    int ty = sp >> 2, tx = sp & 3;
    int y0 = ty * 8, x0 = tx * 16;

    int tid = threadIdx.x;
    int pxg = tid & 15;
    int cog = tid >> 4;                 // 0..7
    int r   = pxg >> 1;                 // 0..7 row within tile
    int chf = (pxg & 1) * 8;            // col half: 0 or 8

    float acc[8][8];
#pragma unroll
    for (int a = 0; a < 8; a++)
#pragma unroll
        for (int b = 0; b < 8; b++) acc[a][b] = 0.f;

    for (int cb = 0; cb < CHN; cb += 8) {
        __syncthreads();
        // input tile: 8 ci x 10 x 18 with zero halo
        for (int idx = tid; idx < 8 * 10 * 18; idx += 128) {
            int ci  = idx / 180;
            int rem = idx - ci * 180;
            int ry  = rem / 18;
            int rx  = rem - ry * 18;
            int gy = y0 + ry - 1, gx = x0 + rx - 1;
            float v = 0.f;
            if (gy >= 0 && gy < HH && gx >= 0 && gx < WW)
                v = in[(cb + ci) * HW + gy * WW + gx];
            xs[(ci * 10 + ry) * 21 + rx] = v;
        }
        // weights: 64 co x (8 ci x 9 taps), coalesced 72-float runs per co
        for (int idx = tid; idx < 64 * 72; idx += 128) {
            int co  = idx / 72;
            int t72 = idx - co * 72;    // = ci*9 + tap
            wsm[t72 * 65 + co] =
                wbase[(coB + co) * 9216 + (w_coff + cb) * 9 + t72];
        }
        __syncthreads();
#pragma unroll 1
        for (int ci = 0; ci < 8; ci++) {
#pragma unroll
            for (int ky = 0; ky < 3; ky++) {
                float xr[10];
#pragma unroll
                for (int j = 0; j < 10; j++)
                    xr[j] = xs[(ci * 10 + r + ky) * 21 + chf + j];
#pragma unroll
                for (int kx = 0; kx < 3; kx++) {
                    float wv[8];
#pragma unroll
                    for (int u = 0; u < 8; u++)
                        wv[u] = wsm[(ci * 9 + ky * 3 + kx) * 65 + u * 8 + cog];
#pragma unroll
                    for (int u = 0; u < 8; u++)
#pragma unroll
                        for (int v = 0; v < 8; v++)
                            acc[u][v] = fmaf(wv[u], xr[v + kx], acc[u][v]);
                }
            }
        }
    }
    int py = y0 + r, pxc = x0 + chf;
#pragma unroll
    for (int u = 0; u < 8; u++) {
        float4* op = reinterpret_cast<float4*>(
            out + (coB + u * 8 + cog) * HW + py * WW + pxc);
        op[0] = make_float4(acc[u][0], acc[u][1], acc[u][2], acc[u][3]);
        op[1] = make_float4(acc[u][4], acc[u][5], acc[u][6], acc[u][7]);
    }
}

// ---------------------------------------------------------------------------
// gather: for node n with children:
//   cs = sum_k h[k];  rh = sum_k sigmoid(Gr + cr_n(pix) + reset_b + R[k]) * h[k]
// ---------------------------------------------------------------------------
__global__ void gather_kernel(int n, const float* __restrict__ reset_b) {
    int cnt = g_childcount[n];
    if (cnt == 0) return;
    int e = blockIdx.x * 256 + threadIdx.x;
    int c = e >> 12;
    int p = e & (HW - 1);
    int y = p >> 6, x = p & 63;
    const float* t = g_t + (0 * NND + n) * 9 * CHN;
    int ky0 = (y == 0), ky1 = 2 - (y == HH - 1);
    int kx0 = (x == 0), kx1 = 2 - (x == WW - 1);
    float cr = 0.f;
    for (int ky = ky0; ky <= ky1; ky++)
        for (int kx = kx0; kx <= kx1; kx++)
            cr += t[(ky * 3 + kx) * CHN + c];
    float base = g_buf[1 * CHW + e] + reset_b[c] + cr;  // Gr
    float cs = 0.f, rh = 0.f;
    for (int j = 0; j < cnt; j++) {
        int k = g_child[n * NND + j];
        float hv = g_buf[(8 + k) * CHW + e];
        float rr = sigm(base + g_buf[(28 + k) * CHW + e]);
        cs += hv;
        rh += rr * hv;
    }
    g_buf[4 * CHW + e] = cs;   // cs
    g_buf[5 * CHW + e] = rh;   // rh
}

// ---------------------------------------------------------------------------
// combine: h[n] = (1-z)*tanh(Go + co_n + output_b + O) + z*cs
//          z    = sigmoid(Gu + cu_n + update_b + U)
// leaves: U = O = cs = 0
// ---------------------------------------------------------------------------
__global__ void combine_kernel(int n, const float* __restrict__ update_b,
                               const float* __restrict__ output_b,
                               float* __restrict__ dst) {
    int e = blockIdx.x * 256 + threadIdx.x;
    int c = e >> 12;
    int p = e & (HW - 1);
    int y = p >> 6, x = p & 63;
    bool haskids = g_childcount[n] > 0;
    const float* tu = g_t + (1 * NND + n) * 9 * CHN;
    const float* to = g_t + (2 * NND + n) * 9 * CHN;
    int ky0 = (y == 0), ky1 = 2 - (y == HH - 1);
    int kx0 = (x == 0), kx1 = 2 - (x == WW - 1);
    float cu = 0.f, co = 0.f;
    for (int ky = ky0; ky <= ky1; ky++)
        for (int kx = kx0; kx <= kx1; kx++) {
            int oidx = (ky * 3 + kx) * CHN + c;
            cu += tu[oidx];
            co += to[oidx];
        }
    float uacc = haskids ? g_buf[6 * CHW + e] : 0.f;
    float oacc = haskids ? g_buf[7 * CHW + e] : 0.f;
    float cs   = haskids ? g_buf[4 * CHW + e] : 0.f;
    float z  = sigm(g_buf[2 * CHW + e] + update_b[c] + cu + uacc);
    float ri = tanhf(g_buf[3 * CHW + e] + output_b[c] + co + oacc);
    dst[e] = (1.f - z) * ri + z * cs;
}

// ---------------------------------------------------------------------------
extern "C" void kernel_launch(void* const* d_in, const int* in_sizes, int n_in,
                              void* d_out, int out_size) {
    const float* vis  = (const float*)d_in[0];
    const float* lang = (const float*)d_in[1];
    const int*   adj  = (const int*)d_in[2];
    const float* mw   = (const float*)d_in[3];
    const float* mb   = (const float*)d_in[4];
    const float* rw   = (const float*)d_in[5];
    const float* rb   = (const float*)d_in[6];
    const float* uw   = (const float*)d_in[7];
    const float* ub   = (const float*)d_in[8];
    const float* ow   = (const float*)d_in[9];
    const float* ob   = (const float*)d_in[10];
    float* out = (float*)d_out;

    float* buf = nullptr;
    cudaGetSymbolAddress((void**)&buf, g_buf);

    dim3 cgrid(32, 8);

    prep_kernel<<<1, 32>>>(adj);
    langbias_kernel<<<40, 256>>>(lang, mw, mb);
    tapconst_kernel<<<54, 256>>>(rw, uw, ow);

    // V = conv1x1(vis, mconv_w[:, :512])   (bias folded into b_n)
    gemm_kernel<<<cgrid, 128>>>(vis, mw, 812, 512, buf);

    // shared convs of V with each gate's x-part weights
    conv3x3_kernel<<<cgrid, 128>>>(buf, rw, 0, buf + 1 * CHW, -1);  // Gr
    conv3x3_kernel<<<cgrid, 128>>>(buf, uw, 0, buf + 2 * CHW, -1);  // Gu
    conv3x3_kernel<<<cgrid, 128>>>(buf, ow, 0, buf + 3 * CHW, -1);  // Go

    // nodes in decreasing index = valid topological order (parent(i) < i)
    for (int n = NND - 1; n >= 0; n--) {
        gather_kernel<<<8192, 256>>>(n, rb);
        // U = conv3x3(cs, Wu_h), O = conv3x3(rh, Wo_h)  (skipped for leaves)
        conv3x3_kernel<<<cgrid, 128>>>(buf + 4 * CHW, uw, 512, buf + 6 * CHW, n);
        conv3x3_kernel<<<cgrid, 128>>>(buf + 5 * CHW, ow, 512, buf + 7 * CHW, n);
        combine_kernel<<<8192, 256>>>(n, ub, ob,
                                      (n == 0) ? out : buf + (8 + n) * CHW);
        if (n > 0)  // R[n] = conv3x3(h[n], Wr_h) for the parent's reset gates
            conv3x3_kernel<<<cgrid, 128>>>(buf + (8 + n) * CHW, rw, 512,
                                           buf + (28 + n) * CHW, -1);
    }
}